// round 2
// baseline (speedup 1.0000x reference)
#include <cuda_runtime.h>
#include <math.h>

#define BB 32
#define NN 384
#define RR 16
#define ROWS_PER_BLOCK 32
#define ROW_CHUNKS (NN / ROWS_PER_BLOCK)            // 12
#define ORDER_BLOCKS (BB * ROW_CHUNKS)              // 384
#define REL_THREADS 256
#define REL_BLOCKS ((BB * NN + REL_THREADS - 1) / REL_THREADS)  // 48

// Atomic-free two-stage reduction scratch (no alloc allowed).
__device__ double g_order_sum[ORDER_BLOCKS];
__device__ double g_order_cnt[ORDER_BLOCKS];
__device__ double g_rel_sum[REL_BLOCKS];
__device__ double g_rel_cnt[REL_BLOCKS];

// ---------------------------------------------------------------------------
// Order BCE kernel: grid = B * (N/ROWS_PER_BLOCK) blocks, 384 threads (= N).
// Thread j handles column j for ROWS_PER_BLOCK consecutive rows i.
// Loads are fully coalesced along j.
// ---------------------------------------------------------------------------
__global__ __launch_bounds__(NN)
void order_kernel(const float* __restrict__ logits,
                  const int* __restrict__ ro,
                  const int* __restrict__ mask) {
    __shared__ int ro_s[NN];
    __shared__ int m_s[NN];

    const int b  = blockIdx.x / ROW_CHUNKS;
    const int i0 = (blockIdx.x % ROW_CHUNKS) * ROWS_PER_BLOCK;
    const int j  = threadIdx.x;

    ro_s[j] = ro[b * NN + j];
    m_s[j]  = mask[b * NN + j];
    __syncthreads();

    const int  ro_j = ro_s[j];
    const bool m_j  = (m_s[j] != 0);

    const float* base = logits + ((size_t)b * NN + i0) * NN + j;

    float fsum = 0.0f;
    int   cnt  = 0;

    #pragma unroll 8
    for (int ii = 0; ii < ROWS_PER_BLOCK; ii++) {
        const int i = i0 + ii;
        const float x = __ldg(base + (size_t)ii * NN);
        const bool valid = m_j && (m_s[i] != 0) && (i != j);
        const float t = (ro_s[i] < ro_j) ? 1.0f : 0.0f;
        // stable softplus: max(x,0) + log(1 + exp(-|x|))
        const float ax = fabsf(x);
        const float sp = fmaxf(x, 0.0f) + __logf(1.0f + __expf(-ax));
        const float bce = sp - x * t;
        if (valid) { fsum += bce; cnt++; }
    }

    // block reduction (12 warps)
    double s = (double)fsum;
    double c = (double)cnt;
    #pragma unroll
    for (int off = 16; off > 0; off >>= 1) {
        s += __shfl_down_sync(0xffffffffu, s, off);
        c += __shfl_down_sync(0xffffffffu, c, off);
    }
    __shared__ double ws[NN / 32];
    __shared__ double wc[NN / 32];
    const int warp = threadIdx.x >> 5;
    const int lane = threadIdx.x & 31;
    if (lane == 0) { ws[warp] = s; wc[warp] = c; }
    __syncthreads();
    if (threadIdx.x == 0) {
        double S = 0.0, C = 0.0;
        #pragma unroll
        for (int w = 0; w < NN / 32; w++) { S += ws[w]; C += wc[w]; }
        g_order_sum[blockIdx.x] = S;
        g_order_cnt[blockIdx.x] = C;
    }
}

// ---------------------------------------------------------------------------
// Relation CE kernel: one thread per (b, i) item; gathers 16 floats
// relation_logits[b, p, i, :] (contiguous, 64B-aligned -> 4x float4).
// ---------------------------------------------------------------------------
__global__ __launch_bounds__(REL_THREADS)
void rel_kernel(const float* __restrict__ rl,
                const int* __restrict__ parent,
                const int* __restrict__ relation,
                const int* __restrict__ mask) {
    const int idx = blockIdx.x * blockDim.x + threadIdx.x;

    float ce = 0.0f;
    int   v  = 0;
    if (idx < BB * NN) {
        const int b = idx / NN;
        const int i = idx - b * NN;
        const int p = parent[idx];
        int       r = relation[idx];
        if (mask[idx] != 0 && p >= 0 && p < NN && r >= 0) {
            r = min(r, RR - 1);
            const float4* row =
                (const float4*)(rl + (((size_t)b * NN + p) * NN + i) * RR);
            float vals[RR];
            float4 v0 = __ldg(row + 0);
            float4 v1 = __ldg(row + 1);
            float4 v2 = __ldg(row + 2);
            float4 v3 = __ldg(row + 3);
            vals[0]=v0.x; vals[1]=v0.y; vals[2]=v0.z; vals[3]=v0.w;
            vals[4]=v1.x; vals[5]=v1.y; vals[6]=v1.z; vals[7]=v1.w;
            vals[8]=v2.x; vals[9]=v2.y; vals[10]=v2.z; vals[11]=v2.w;
            vals[12]=v3.x; vals[13]=v3.y; vals[14]=v3.z; vals[15]=v3.w;
            float m = vals[0];
            #pragma unroll
            for (int k = 1; k < RR; k++) m = fmaxf(m, vals[k]);
            float ssum = 0.0f;
            #pragma unroll
            for (int k = 0; k < RR; k++) ssum += __expf(vals[k] - m);
            ce = m + __logf(ssum) - vals[r];
            v = 1;
        }
    }

    double s = (double)ce;
    double c = (double)v;
    #pragma unroll
    for (int off = 16; off > 0; off >>= 1) {
        s += __shfl_down_sync(0xffffffffu, s, off);
        c += __shfl_down_sync(0xffffffffu, c, off);
    }
    __shared__ double ws[REL_THREADS / 32];
    __shared__ double wc[REL_THREADS / 32];
    const int warp = threadIdx.x >> 5;
    const int lane = threadIdx.x & 31;
    if (lane == 0) { ws[warp] = s; wc[warp] = c; }
    __syncthreads();
    if (threadIdx.x == 0) {
        double S = 0.0, C = 0.0;
        #pragma unroll
        for (int w = 0; w < REL_THREADS / 32; w++) { S += ws[w]; C += wc[w]; }
        g_rel_sum[blockIdx.x] = S;
        g_rel_cnt[blockIdx.x] = C;
    }
}

// ---------------------------------------------------------------------------
// Finalize: one warp reduces all partials and writes the three scalars.
// ---------------------------------------------------------------------------
__global__ void finalize_kernel(float* __restrict__ out, int out_size) {
    const int lane = threadIdx.x;
    double os = 0.0, oc = 0.0, rs = 0.0, rc = 0.0;
    for (int k = lane; k < ORDER_BLOCKS; k += 32) {
        os += g_order_sum[k];
        oc += g_order_cnt[k];
    }
    for (int k = lane; k < REL_BLOCKS; k += 32) {
        rs += g_rel_sum[k];
        rc += g_rel_cnt[k];
    }
    #pragma unroll
    for (int off = 16; off > 0; off >>= 1) {
        os += __shfl_down_sync(0xffffffffu, os, off);
        oc += __shfl_down_sync(0xffffffffu, oc, off);
        rs += __shfl_down_sync(0xffffffffu, rs, off);
        rc += __shfl_down_sync(0xffffffffu, rc, off);
    }
    if (lane == 0) {
        const double order_loss = os / fmax(oc, 1.0);
        const double rel_loss   = rs / fmax(rc, 1.0);
        const double total = 1.0 * order_loss + 0.5 * rel_loss;
        out[0] = (float)total;
        if (out_size > 1) out[1] = (float)order_loss;
        if (out_size > 2) out[2] = (float)rel_loss;
    }
}

extern "C" void kernel_launch(void* const* d_in, const int* in_sizes, int n_in,
                              void* d_out, int out_size) {
    const float* order_logits    = (const float*)d_in[0];
    const float* relation_logits = (const float*)d_in[1];
    const int*   reading_orders  = (const int*)d_in[2];
    const int*   parent_ids      = (const int*)d_in[3];
    const int*   relations       = (const int*)d_in[4];
    const int*   region_mask     = (const int*)d_in[5];
    float* out = (float*)d_out;

    order_kernel<<<ORDER_BLOCKS, NN>>>(order_logits, reading_orders, region_mask);
    rel_kernel<<<REL_BLOCKS, REL_THREADS>>>(relation_logits, parent_ids,
                                            relations, region_mask);
    finalize_kernel<<<1, 32>>>(out, out_size);
}